// round 8
// baseline (speedup 1.0000x reference)
#include <cuda_runtime.h>
#include <cuda_fp16.h>
#include <cstdint>

#define N_ROWS 131072
#define K_CODES 4096
#define DIM 64
#define MT 256            // rows per CTA
#define NC 128            // codes per chunk
#define NCH (K_CODES/NC)  // 32
#define CAP 128           // candidate slots per row
#define QCAP 16           // per writer (8 writers/row)
#define NW 8
#define MARG_S 1.6384f    // 4e-4 * 4096 (emb pre-scaled by 2^12)

// ---------------- device scratch (no allocation allowed) ----------------
__device__ float          g_zz[N_ROWS];
__device__ float          g_ee[K_CODES];
__device__ int            g_idx[N_ROWS];
__device__ double         g_loss;
__device__ __align__(16) __half g_zh[(size_t)N_ROWS * DIM];
__device__ __align__(16) __half g_eh[(size_t)K_CODES * DIM];   // scaled by 4096
__device__ int            g_cand[(size_t)N_ROWS * CAP];
__device__ int            g_cnt[(size_t)N_ROWS * NW];

// ---------------- PTX helpers ----------------
__device__ __forceinline__ uint32_t smem_u32(const void* p) {
    uint32_t a;
    asm("{ .reg .u64 t; cvta.to.shared.u64 t, %1; cvt.u32.u64 %0, t; }" : "=r"(a) : "l"(p));
    return a;
}
#define SMEM_SWIZZLE_128B(o) ((o) ^ (((o) >> 3) & 0x70))

#define LDMATRIX_X4(r, a) \
    asm volatile("ldmatrix.sync.aligned.m8n8.x4.shared.b16 {%0,%1,%2,%3}, [%4];" \
        : "=r"((r)[0]), "=r"((r)[1]), "=r"((r)[2]), "=r"((r)[3]) : "r"(a))

#define MMA_F16(c, a, b0, b1) \
    asm volatile("mma.sync.aligned.m16n8k16.row.col.f16.f16.f16.f16 " \
        "{%0,%1}, {%2,%3,%4,%5}, {%6,%7}, {%0,%1};" \
        : "+r"((c)[0]), "+r"((c)[1]) \
        : "r"((a)[0]), "r"((a)[1]), "r"((a)[2]), "r"((a)[3]), "r"(b0), "r"(b1))

#define CP_ASYNC16(sa, gp) \
    asm volatile("cp.async.cg.shared.global [%0], [%1], 16;" :: "r"((uint32_t)(sa)), "l"(gp) : "memory")
#define CP_COMMIT()  asm volatile("cp.async.commit_group;" ::: "memory")
#define CP_WAITG(n)  asm volatile("cp.async.wait_group %0;" :: "n"(n) : "memory")

#define NEG_INF __int_as_float(0xff800000)

// ---------------------------------------------------------------------------
// prep: warp per row. zz/ee (fp32 via double) + f16 conversion.
// emb scaled by 2^12 (exact power of two) to land in f16 normal range.
// ---------------------------------------------------------------------------
__global__ void vq_prep(const float* __restrict__ z, const float* __restrict__ emb) {
    int wid = threadIdx.x >> 5, lane = threadIdx.x & 31;
    int r = blockIdx.x * 8 + wid;
    if (blockIdx.x == 0 && threadIdx.x == 0) g_loss = 0.0;
    if (r >= N_ROWS + K_CODES) return;
    if (r < N_ROWS) {
        const float* src = z + (size_t)r * DIM;
        float2 v = ((const float2*)src)[lane];
        ((__half2*)(g_zh + (size_t)r * DIM))[lane] = __floats2half2_rn(v.x, v.y);
        double s = (double)__fmul_rn(v.x, v.x) + (double)__fmul_rn(v.y, v.y);
        #pragma unroll
        for (int off = 16; off; off >>= 1) s += __shfl_down_sync(0xffffffffu, s, off);
        if (lane == 0) g_zz[r] = (float)s;
    } else {
        int rr = r - N_ROWS;
        const float* src = emb + (size_t)rr * DIM;
        float2 v = ((const float2*)src)[lane];
        ((__half2*)(g_eh + (size_t)rr * DIM))[lane] =
            __floats2half2_rn(v.x * 4096.0f, v.y * 4096.0f);
        double s = (double)__fmul_rn(v.x, v.x) + (double)__fmul_rn(v.y, v.y);
        #pragma unroll
        for (int off = 16; off; off >>= 1) s += __shfl_down_sync(0xffffffffu, s, off);
        if (lane == 0) g_ee[rr] = (float)s;
    }
}

// ---------------------------------------------------------------------------
// pass 1: f16/f16-accum mma.sync, 512 threads, warp grid 8(m)x2(n),
// warp tile 32 rows x 64 codes (mt=2). Packed-half max tree; scalar
// half compare pre-filter (conservative core intrinsics only).
// ---------------------------------------------------------------------------
extern __shared__ char sm_dyn[];

__global__ void __launch_bounds__(512)
vq_pass1() {
    const int tid = threadIdx.x;
    const int lane = tid & 31;
    const int wid = tid >> 5;
    const int warp_m = wid & 7;
    const int warp_n = wid >> 3;
    const int rowBase = blockIdx.x * MT;

    uint32_t dynb = smem_u32(sm_dyn);
    uint32_t uZ = (dynb + 127u) & ~127u;    // Z: 256 rows x 128B (swizzled)
    uint32_t uE = uZ + MT * 128;            // E: 2 x (128 x 128B)

    // prologue: Z (2048 segs) + E0, E1 (1024 segs each)
    {
        const char* zsrc = (const char*)g_zh + (size_t)rowBase * 128;
        #pragma unroll
        for (int i = 0; i < 4; i++) {
            uint32_t off = (uint32_t)(tid + i * 512) * 16;
            CP_ASYNC16(uZ + SMEM_SWIZZLE_128B(off), zsrc + off);
        }
        const char* e0 = (const char*)g_eh;
        #pragma unroll
        for (int i = 0; i < 2; i++) {
            uint32_t off = (uint32_t)(tid + i * 512) * 16;
            CP_ASYNC16(uE + SMEM_SWIZZLE_128B(off), e0 + off);
        }
        CP_COMMIT();
        const char* e1 = (const char*)g_eh + NC * 128;
        #pragma unroll
        for (int i = 0; i < 2; i++) {
            uint32_t off = (uint32_t)(tid + i * 512) * 16;
            CP_ASYNC16(uE + 16384 + SMEM_SWIZZLE_128B(off), e1 + off);
        }
        CP_COMMIT();
    }
    CP_WAITG(1);
    __syncthreads();

    // A fragments: resident (two m16 tiles per warp)
    uint32_t afr[2][4][4];
    #pragma unroll
    for (int mt = 0; mt < 2; mt++)
        #pragma unroll
        for (int kt = 0; kt < 4; kt++) {
            int row = warp_m * 32 + mt * 16 + (lane & 15);
            uint32_t ch = (uint32_t)(kt * 2 + (lane >> 4));
            uint32_t addr = uZ + (uint32_t)row * 128 + ((ch ^ (uint32_t)(row & 7)) * 16);
            LDMATRIX_X4(afr[mt][kt], addr);
        }

    // argmax state: 4 row-slots s = mt*2+p -> row r0 + mt*16 + p*8
    const int w = warp_n * 4 + (lane & 3);
    const int r0 = rowBase + warp_m * 32 + (lane >> 2);
    float rmax[4] = {NEG_INF, NEG_INF, NEG_INF, NEG_INF};
    int cnt[4] = {0, 0, 0, 0};
    int* sp[4];
    #pragma unroll
    for (int s = 0; s < 4; s++) {
        int mt = s >> 1, p = s & 1;
        sp[s] = g_cand + (size_t)(r0 + mt * 16 + p * 8) * CAP + w * QCAP;
    }

    for (int c = 0; c < NCH; c++) {
        if (c) { CP_WAITG(1); __syncthreads(); }
        const uint32_t eb = uE + (uint32_t)(c & 1) * 16384;

        uint32_t acc[2][8][2];
        #pragma unroll
        for (int mt = 0; mt < 2; mt++)
            #pragma unroll
            for (int nt = 0; nt < 8; nt++) { acc[mt][nt][0] = 0u; acc[mt][nt][1] = 0u; }

        #pragma unroll
        for (int nt = 0; nt < 8; nt++) {
            uint32_t bfr[8];
            #pragma unroll
            for (int kp = 0; kp < 2; kp++) {
                int row = warp_n * 64 + nt * 8 + (lane & 7);
                uint32_t ch = (uint32_t)(kp * 4 + (lane >> 3));
                uint32_t addr = eb + (uint32_t)row * 128 + ((ch ^ (uint32_t)(row & 7)) * 16);
                LDMATRIX_X4(&bfr[kp * 4], addr);
            }
            #pragma unroll
            for (int mt = 0; mt < 2; mt++)
                #pragma unroll
                for (int kt = 0; kt < 4; kt++)
                    MMA_F16(acc[mt][nt], afr[mt][kt], bfr[kt * 2], bfr[kt * 2 + 1]);
        }

        __syncthreads();                      // all warps done reading E[c&1]
        if (c + 2 < NCH) {                    // prefetch E[c+2] into buf c&1
            const char* en = (const char*)g_eh + (size_t)(c + 2) * (NC * 128);
            uint32_t sb = uE + (uint32_t)(c & 1) * 16384;
            #pragma unroll
            for (int i = 0; i < 2; i++) {
                uint32_t off = (uint32_t)(tid + i * 512) * 16;
                CP_ASYNC16(sb + SMEM_SWIZZLE_128B(off), en + off);
            }
        }
        CP_COMMIT();                          // uniform group counts

        // ---- phase 1: packed hmax2 tree per slot, quad shfl, threshold ----
        float thrf[4];
        __half thrh[4];
        #pragma unroll
        for (int s = 0; s < 4; s++) {
            int mt = s >> 1, p = s & 1;
            __half2 hm = *(__half2*)&acc[mt][0][p];
            #pragma unroll
            for (int nt = 1; nt < 8; nt++)
                hm = __hmax2(hm, *(__half2*)&acc[mt][nt][p]);
            float cm = __half2float(__hmax(__low2half(hm), __high2half(hm)));
            cm = fmaxf(cm, __shfl_xor_sync(0xffffffffu, cm, 1));
            cm = fmaxf(cm, __shfl_xor_sync(0xffffffffu, cm, 2));
            rmax[s] = fmaxf(rmax[s], cm);
            thrf[s] = __fadd_rn(rmax[s], -MARG_S);
            thrh[s] = __float2half_rd(thrf[s]);   // rd: superset-safe in half compare
        }

        // ---- phase 2: pair max pre-filter, rare-hit scalar unpack ----
        #pragma unroll
        for (int nt = 0; nt < 8; nt++) {
            const int colb = c * NC + warp_n * 64 + nt * 8 + (lane & 3) * 2;
            #pragma unroll
            for (int mt = 0; mt < 2; mt++)
                #pragma unroll
                for (int p = 0; p < 2; p++) {
                    const int s = mt * 2 + p;
                    __half2 pv = *(__half2*)&acc[mt][nt][p];
                    __half mx = __hmax(__low2half(pv), __high2half(pv));
                    if (__hgt(mx, thrh[s])) {            // at least one may exceed thr
                        float v0 = __low2float(pv);
                        float v1 = __high2float(pv);
                        if (v0 > thrf[s]) { if (cnt[s] < QCAP) sp[s][cnt[s]] = colb;     cnt[s]++; }
                        if (v1 > thrf[s]) { if (cnt[s] < QCAP) sp[s][cnt[s]] = colb + 1; cnt[s]++; }
                    }
                }
        }
    }

    #pragma unroll
    for (int s = 0; s < 4; s++) {
        int mt = s >> 1, p = s & 1;
        g_cnt[(size_t)(r0 + mt * 16 + p * 8) * NW + w] = cnt[s];  // raw
    }
}

// ---------------------------------------------------------------------------
// rescore: warp per row; slot-mask iteration, exact serial-FMA distance
// (bit-identical to R1, which matched exactly). Overflow -> full scan.
// ---------------------------------------------------------------------------
__global__ void __launch_bounds__(256)
vq_rescore(const float* __restrict__ z, const float* __restrict__ emb) {
    __shared__ float zs[8][DIM];
    const int wid = threadIdx.x >> 5, lane = threadIdx.x & 31;
    const int row = blockIdx.x * 8 + wid;

    float2 v = ((const float2*)(z + (size_t)row * DIM))[lane];
    zs[wid][2 * lane] = v.x;
    zs[wid][2 * lane + 1] = v.y;
    __syncwarp();

    int myc = (lane < NW) ? g_cnt[(size_t)row * NW + lane] : 0;
    bool ovf = __any_sync(0xffffffffu, myc > QCAP);

    const float zzr = g_zz[row];
    const int* cbase = g_cand + (size_t)row * CAP;
    float best = __int_as_float(0x7f800000);
    int bidx = 0x7fffffff;

    if (!ovf) {
        #pragma unroll
        for (int it = 0; it < 4; it++) {
            int slot = lane + it * 32;
            int sw = slot >> 4;               // writer (QCAP = 16)
            int j  = slot & 15;
            int cw = __shfl_sync(0xffffffffu, myc, sw);
            if (j < cw) {
                int cand = cbase[slot];
                const float4* e4 = (const float4*)(emb + (size_t)cand * DIM);
                float s = 0.0f;
                #pragma unroll
                for (int q = 0; q < 16; q++) {
                    float4 e = __ldg(e4 + q);
                    s = __fmaf_rn(zs[wid][4 * q + 0], e.x, s);
                    s = __fmaf_rn(zs[wid][4 * q + 1], e.y, s);
                    s = __fmaf_rn(zs[wid][4 * q + 2], e.z, s);
                    s = __fmaf_rn(zs[wid][4 * q + 3], e.w, s);
                }
                float t = __fadd_rn(zzr, g_ee[cand]);
                float d = __fmaf_rn(-2.0f, s, t);
                if (d < best || (d == best && cand < bidx)) { best = d; bidx = cand; }
            }
        }
    } else {
        for (int cand = lane; cand < K_CODES; cand += 32) {
            const float4* e4 = (const float4*)(emb + (size_t)cand * DIM);
            float s = 0.0f;
            #pragma unroll
            for (int q = 0; q < 16; q++) {
                float4 e = __ldg(e4 + q);
                s = __fmaf_rn(zs[wid][4 * q + 0], e.x, s);
                s = __fmaf_rn(zs[wid][4 * q + 1], e.y, s);
                s = __fmaf_rn(zs[wid][4 * q + 2], e.z, s);
                s = __fmaf_rn(zs[wid][4 * q + 3], e.w, s);
            }
            float t = __fadd_rn(zzr, g_ee[cand]);
            float d = __fmaf_rn(-2.0f, s, t);
            if (d < best || (d == best && cand < bidx)) { best = d; bidx = cand; }
        }
    }
    #pragma unroll
    for (int off = 16; off >= 1; off >>= 1) {
        float od = __shfl_xor_sync(0xffffffffu, best, off);
        int   oi = __shfl_xor_sync(0xffffffffu, bidx, off);
        if (od < best || (od == best && oi < bidx)) { best = od; bidx = oi; }
    }
    if (lane == 0) g_idx[row] = (bidx == 0x7fffffff) ? 0 : bidx;
}

// ---------------------------------------------------------------------------
// output + loss: float4-vectorized, same rounding as R1.
// ---------------------------------------------------------------------------
__global__ void vq_output(const float* __restrict__ z, const float* __restrict__ emb,
                          float* __restrict__ out, long long outSize) {
    long long t  = (long long)blockIdx.x * blockDim.x + threadIdx.x;   // 16B segs
    long long nd = (long long)N_ROWS * DIM;
    long long nseg = nd >> 2;
    double sq = 0.0;
    if (t < nseg) {
        int row = (int)(t >> 4);
        int seg = (int)(t & 15);
        int idx = g_idx[row];
        float4 e  = __ldg((const float4*)(emb + (size_t)idx * DIM) + seg);
        float4 zv = ((const float4*)z)[t];
        float dx = __fsub_rn(e.x, zv.x), dy = __fsub_rn(e.y, zv.y);
        float dz = __fsub_rn(e.z, zv.z), dw = __fsub_rn(e.w, zv.w);
        if (t * 4 + 3 < outSize) {
            float4 o;
            o.x = __fadd_rn(zv.x, dx); o.y = __fadd_rn(zv.y, dy);
            o.z = __fadd_rn(zv.z, dz); o.w = __fadd_rn(zv.w, dw);
            ((float4*)out)[t] = o;
        }
        sq = (double)__fmul_rn(dx, dx) + (double)__fmul_rn(dy, dy)
           + (double)__fmul_rn(dz, dz) + (double)__fmul_rn(dw, dw);
        if (t < N_ROWS && nd + t < outSize) out[nd + t] = (float)g_idx[(int)t];
    }
    #pragma unroll
    for (int off = 16; off >= 1; off >>= 1) sq += __shfl_down_sync(0xffffffffu, sq, off);
    __shared__ double wsum[8];
    int lane = threadIdx.x & 31, wid = threadIdx.x >> 5;
    if (lane == 0) wsum[wid] = sq;
    __syncthreads();
    if (threadIdx.x == 0) {
        double b = 0.0;
        #pragma unroll
        for (int w = 0; w < 8; w++) b += wsum[w];
        atomicAdd(&g_loss, b);
    }
}

__global__ void vq_finalize(float* __restrict__ out, long long outSize) {
    long long nd = (long long)N_ROWS * DIM;
    if (nd + N_ROWS < outSize) {
        float mf = (float)(g_loss / (double)nd);
        out[nd + N_ROWS] = __fmaf_rn(0.5f, mf, mf);
    }
}

// ---------------------------------------------------------------------------
extern "C" void kernel_launch(void* const* d_in, const int* in_sizes, int n_in,
                              void* d_out, int out_size) {
    const float* z   = (const float*)d_in[0];
    const float* emb = (const float*)d_in[1];
    float* out = (float*)d_out;

    const int dynSmem = 128 + MT * 128 + 2 * (NC * 128);  // ~64.1 KB
    cudaFuncSetAttribute(vq_pass1, cudaFuncAttributeMaxDynamicSharedMemorySize, dynSmem);

    vq_prep<<<(N_ROWS + K_CODES) / 8, 256>>>(z, emb);
    vq_pass1<<<N_ROWS / MT, 512, dynSmem>>>();
    vq_rescore<<<N_ROWS / 8, 256>>>(z, emb);
    long long nd = (long long)N_ROWS * DIM;
    long long nseg = nd >> 2;
    vq_output<<<(int)((nseg + 255) / 256), 256>>>(z, emb, out, (long long)out_size);
    vq_finalize<<<1, 1>>>(out, (long long)out_size);
}